// round 3
// baseline (speedup 1.0000x reference)
#include <cuda_runtime.h>
#include <cuda_bf16.h>
#include <cstdint>

// ---------------------------------------------------------------------------
// Problem constants
// ---------------------------------------------------------------------------
#define N_BATCH 8192
#define N_IN    784
#define N_HID   4096
#define N_OUT   10
#define KP      832      // K padded to 13 * 64
#define KCH     13       // number of 64-column K chunks

// ---------------------------------------------------------------------------
// Device scratch (static: no allocation allowed)
// ---------------------------------------------------------------------------
__device__ __align__(16) __nv_bfloat16 g_xhi[(size_t)N_BATCH * KP];
__device__ __align__(16) __nv_bfloat16 g_xlo[(size_t)N_BATCH * KP];
__device__ __align__(16) __nv_bfloat16 g_wb [(size_t)N_HID   * KP];
// partials: [64 m-blocks][64 n-chunks of 64 cols][128 rows][10 outs]
__device__ float g_part[(size_t)64 * 64 * 128 * N_OUT];

// ---------------------------------------------------------------------------
// Helpers (base sm_103-legal only: cp.async, ldmatrix, mma.sync)
// ---------------------------------------------------------------------------
__device__ __forceinline__ uint32_t smem_to_u32(const void* smem_ptr) {
    uint32_t addr;
    asm("{ .reg .u64 tmp; cvta.to.shared.u64 tmp, %1; cvt.u32.u64 %0, tmp; }"
        : "=r"(addr) : "l"(smem_ptr));
    return addr;
}

__device__ __forceinline__ void cp_async16(uint32_t saddr, const void* gptr) {
    asm volatile("cp.async.cg.shared.global [%0], [%1], 16;"
                 :: "r"(saddr), "l"(gptr));
}
#define CP_COMMIT() asm volatile("cp.async.commit_group;" ::: "memory")
#define CP_WAIT(n)  asm volatile("cp.async.wait_group %0;" :: "n"(n) : "memory")

__device__ __forceinline__ void ldsm_x4(uint32_t& r0, uint32_t& r1,
                                        uint32_t& r2, uint32_t& r3,
                                        uint32_t addr) {
    asm volatile("ldmatrix.sync.aligned.m8n8.x4.shared.b16 {%0,%1,%2,%3}, [%4];"
                 : "=r"(r0), "=r"(r1), "=r"(r2), "=r"(r3) : "r"(addr));
}
__device__ __forceinline__ void ldsm_x2(uint32_t& r0, uint32_t& r1,
                                        uint32_t addr) {
    asm volatile("ldmatrix.sync.aligned.m8n8.x2.shared.b16 {%0,%1}, [%2];"
                 : "=r"(r0), "=r"(r1) : "r"(addr));
}

__device__ __forceinline__ void mma16816(float* c, const uint32_t* a,
                                         const uint32_t* b) {
    asm volatile(
        "mma.sync.aligned.m16n8k16.row.col.f32.bf16.bf16.f32 "
        "{%0,%1,%2,%3}, {%4,%5,%6,%7}, {%8,%9}, {%0,%1,%2,%3};"
        : "+f"(c[0]), "+f"(c[1]), "+f"(c[2]), "+f"(c[3])
        : "r"(a[0]), "r"(a[1]), "r"(a[2]), "r"(a[3]), "r"(b[0]), "r"(b[1]));
}

__device__ __forceinline__ uint32_t sw128(uint32_t b) {
    return b ^ ((b >> 3) & 0x70);
}

// ---------------------------------------------------------------------------
// Prep kernels: binarize W1, split x into bf16 hi/lo, pad K to 832
// ---------------------------------------------------------------------------
__global__ void prep_w_kernel(const float* __restrict__ W1) {
    int idx = blockIdx.x * blockDim.x + threadIdx.x;
    if (idx >= N_HID * KP) return;
    int r = idx / KP, k = idx - r * KP;
    float s = 0.0f;
    if (k < N_IN) {
        float w = W1[(size_t)r * N_IN + k];
        s = (w > 0.0f) ? 1.0f : ((w < 0.0f) ? -1.0f : 0.0f);
    }
    g_wb[idx] = __float2bfloat16(s);
}

__global__ void prep_x_kernel(const float* __restrict__ x) {
    int idx = blockIdx.x * blockDim.x + threadIdx.x;
    if (idx >= N_BATCH * KP) return;
    int r = idx / KP, k = idx - r * KP;
    __nv_bfloat16 hi = __float2bfloat16(0.0f);
    __nv_bfloat16 lo = __float2bfloat16(0.0f);
    if (k < N_IN) {
        float v = x[(size_t)r * N_IN + k];
        hi = __float2bfloat16(v);
        lo = __float2bfloat16(v - __bfloat162float(hi));
    }
    g_xhi[idx] = hi;
    g_xlo[idx] = lo;
}

// ---------------------------------------------------------------------------
// Fused GEMM1 (+bias, clip) + partial GEMM2 kernel
// Grid: (32 n-blocks of 128, 64 m-blocks of 128), 256 threads/CTA
// CTA tile 128x128, warps 2(M) x 4(N), warp tile 64x32, mma m16n8k16 bf16
// ---------------------------------------------------------------------------
#define SMEM_B1     0                    // 128 floats
#define SMEM_W2     512                  // 10*128 floats = 5120 B
#define SMEM_T0     6144                 // stage 0: Ah,Al,B (16 KB each)
#define SMEM_T1     (SMEM_T0 + 49152)    // stage 1
#define SMEM_H      SMEM_T0              // reuse for h tile: 128*132*4 B
#define SMEM_TOTAL  (SMEM_T1 + 49152)    // 104448 B

__global__ void __launch_bounds__(256)
gemm_fused_kernel(const float* __restrict__ b1, const float* __restrict__ W2)
{
    extern __shared__ char smem[];
    const uint32_t smem_base = smem_to_u32(smem);
    const int tid = threadIdx.x;
    const int wid = tid >> 5;
    const int lid = tid & 31;
    const int nb  = blockIdx.x;       // n-block: 128 hidden cols
    const int mb  = blockIdx.y;       // m-block: 128 batch rows
    const int nbase = nb * 128;

    // stage b1 and W2 slices for this n-range
    {
        float* b1s = reinterpret_cast<float*>(smem + SMEM_B1);
        float* w2s = reinterpret_cast<float*>(smem + SMEM_W2);
        if (tid < 128) b1s[tid] = b1[nbase + tid];
        for (int i = tid; i < N_OUT * 128; i += 256) {
            int o = i >> 7, n = i & 127;
            w2s[i] = W2[(size_t)o * N_HID + nbase + n];
        }
    }

    const __nv_bfloat16* Ah = g_xhi + (size_t)mb * 128 * KP;
    const __nv_bfloat16* Al = g_xlo + (size_t)mb * 128 * KP;
    const __nv_bfloat16* Bw = g_wb  + (size_t)nbase * KP;

    // async-load one 48 KB chunk (A_hi, A_lo: 128 rows; B: 128 rows; 128 B/row)
    auto load_chunk = [&](int kc, uint32_t stage) {
        const int kco = kc * 64;
        #pragma unroll
        for (int t = tid; t < 128 * 8; t += 256) {
            int r = t >> 3, i = t & 7;
            uint32_t so = sw128((r << 7) | (i << 4));
            cp_async16(stage + so,           Ah + (size_t)r * KP + kco + i * 8);
            cp_async16(stage + 16384 + so,   Al + (size_t)r * KP + kco + i * 8);
            cp_async16(stage + 32768 + so,   Bw + (size_t)r * KP + kco + i * 8);
        }
    };

    const int wm = wid >> 2;    // 0..1
    const int wn = wid & 3;     // 0..3

    float c[16][4];
    #pragma unroll
    for (int t = 0; t < 16; t++)
        #pragma unroll
        for (int a = 0; a < 4; a++) c[t][a] = 0.0f;

    load_chunk(0, smem_base + SMEM_T0);
    CP_COMMIT();

    // precomputed ldmatrix lane offsets (within a tile, before swizzle)
    const uint32_t a_row = (uint32_t)(lid & 15);          // + m-tile base
    const uint32_t a_byt = (uint32_t)((lid >> 4) << 4);   // 0 or 16
    const uint32_t b_row = (uint32_t)(lid & 7);           // + n-tile base
    const uint32_t b_byt = (uint32_t)(((lid >> 3) & 1) << 4);

    for (int kc = 0; kc < KCH; kc++) {
        if (kc + 1 < KCH) {
            load_chunk(kc + 1, smem_base + ((kc + 1) & 1 ? SMEM_T1 : SMEM_T0));
            CP_COMMIT();
            CP_WAIT(1);
        } else {
            CP_WAIT(0);
        }
        __syncthreads();

        const uint32_t stage = smem_base + ((kc & 1) ? SMEM_T1 : SMEM_T0);
        const uint32_t sa_hi = stage;
        const uint32_t sa_lo = stage + 16384;
        const uint32_t sb    = stage + 32768;

        #pragma unroll
        for (int s = 0; s < 4; s++) {
            const uint32_t kbyt = s * 32;
            uint32_t bf[4][2];
            #pragma unroll
            for (int j = 0; j < 4; j++) {
                uint32_t nrow = wn * 32 + j * 8 + b_row;
                ldsm_x2(bf[j][0], bf[j][1],
                        sb + sw128((nrow << 7) + kbyt + b_byt));
            }
            #pragma unroll
            for (int i = 0; i < 4; i++) {
                uint32_t af[4];
                uint32_t arow = wm * 64 + i * 16 + a_row;
                ldsm_x4(af[0], af[1], af[2], af[3],
                        sa_hi + sw128((arow << 7) + kbyt + a_byt));
                #pragma unroll
                for (int j = 0; j < 4; j++) mma16816(c[i * 4 + j], af, bf[j]);
            }
            #pragma unroll
            for (int i = 0; i < 4; i++) {
                uint32_t af[4];
                uint32_t arow = wm * 64 + i * 16 + a_row;
                ldsm_x4(af[0], af[1], af[2], af[3],
                        sa_lo + sw128((arow << 7) + kbyt + a_byt));
                #pragma unroll
                for (int j = 0; j < 4; j++) mma16816(c[i * 4 + j], af, bf[j]);
            }
        }
        __syncthreads();
    }

    // ---- epilogue: +b1, clip -> h tile in smem (stride 132 floats) ----
    {
        const float* b1s = reinterpret_cast<const float*>(smem + SMEM_B1);
        float* hs = reinterpret_cast<float*>(smem + SMEM_H);
        #pragma unroll
        for (int i = 0; i < 4; i++) {
            #pragma unroll
            for (int j = 0; j < 4; j++) {
                int r0 = wm * 64 + i * 16 + (lid >> 2);
                int cc = wn * 32 + j * 8 + (lid & 3) * 2;
                float bb0 = b1s[cc], bb1 = b1s[cc + 1];
                float v0 = fminf(1.0f, fmaxf(-1.0f, c[i * 4 + j][0] + bb0));
                float v1 = fminf(1.0f, fmaxf(-1.0f, c[i * 4 + j][1] + bb1));
                float v2 = fminf(1.0f, fmaxf(-1.0f, c[i * 4 + j][2] + bb0));
                float v3 = fminf(1.0f, fmaxf(-1.0f, c[i * 4 + j][3] + bb1));
                hs[r0 * 132 + cc]           = v0;
                hs[r0 * 132 + cc + 1]       = v1;
                hs[(r0 + 8) * 132 + cc]     = v2;
                hs[(r0 + 8) * 132 + cc + 1] = v3;
            }
        }
    }
    __syncthreads();

    // ---- partial GEMM2: thread = (row, half of 64 cols) -> g_part ----
    {
        const int row  = tid >> 1;
        const int half = tid & 1;
        const float* hrow =
            reinterpret_cast<const float*>(smem + SMEM_H) + row * 132 + half * 64;
        const float* w2s =
            reinterpret_cast<const float*>(smem + SMEM_W2) + half * 64;

        float acc[N_OUT];
        #pragma unroll
        for (int o = 0; o < N_OUT; o++) acc[o] = 0.0f;
        #pragma unroll 8
        for (int cidx = 0; cidx < 64; cidx++) {
            float h = hrow[cidx];
            #pragma unroll
            for (int o = 0; o < N_OUT; o++) acc[o] += h * w2s[o * 128 + cidx];
        }
        const size_t pb =
            ((size_t)(mb * 64 + nb * 2 + half) * 128 + row) * N_OUT;
        #pragma unroll
        for (int o = 0; o < N_OUT; o++) g_part[pb + o] = acc[o];
    }
}

// ---------------------------------------------------------------------------
// Final reduce: out[m,o] = b2[o] + sum over 64 n-chunks of partials
// ---------------------------------------------------------------------------
__global__ void reduce_kernel(const float* __restrict__ b2,
                              float* __restrict__ out)
{
    int idx = blockIdx.x * blockDim.x + threadIdx.x;
    if (idx >= N_BATCH * N_OUT) return;
    int m = idx / N_OUT, o = idx - m * N_OUT;
    int mb = m >> 7, r = m & 127;
    float s = b2[o];
    const float* p = g_part + ((size_t)(mb * 64) * 128 + r) * N_OUT + o;
    #pragma unroll
    for (int nc = 0; nc < 64; nc++) s += p[(size_t)nc * 128 * N_OUT];
    out[idx] = s;
}

// ---------------------------------------------------------------------------
// kernel_launch
// ---------------------------------------------------------------------------
extern "C" void kernel_launch(void* const* d_in, const int* in_sizes, int n_in,
                              void* d_out, int out_size)
{
    const float* x  = (const float*)d_in[0];
    const float* W1 = (const float*)d_in[1];
    const float* b1 = (const float*)d_in[2];
    const float* W2 = (const float*)d_in[3];
    const float* b2 = (const float*)d_in[4];
    float* out = (float*)d_out;

    cudaFuncSetAttribute(gemm_fused_kernel,
                         cudaFuncAttributeMaxDynamicSharedMemorySize, SMEM_TOTAL);

    prep_x_kernel<<<(N_BATCH * KP + 255) / 256, 256>>>(x);
    prep_w_kernel<<<(N_HID * KP + 255) / 256, 256>>>(W1);
    gemm_fused_kernel<<<dim3(32, 64), 256, SMEM_TOTAL>>>(b1, W2);
    reduce_kernel<<<(N_BATCH * N_OUT + 255) / 256, 256>>>(b2, out);
}